// round 2
// baseline (speedup 1.0000x reference)
#include <cuda_runtime.h>
#include <math.h>

#define Hs   128
#define Ws   128
#define Cs   64
#define Os   64
#define HW   16384
#define Q    576          // Cs * 9

typedef unsigned long long u64;

// offsets, layout [k][b*HW][2] : coalesced float2 reads in deform sampler
__device__ float g_off[9 * 4 * HW * 2];

// ---------------- packed f32x2 helpers (sm_100+) ----------------
__device__ __forceinline__ u64 pack2(float lo, float hi) {
    u64 r;
    asm("mov.b64 %0, {%1, %2};" : "=l"(r) : "f"(lo), "f"(hi));
    return r;
}
__device__ __forceinline__ void unpack2(u64 v, float& lo, float& hi) {
    asm("mov.b64 {%0, %1}, %2;" : "=f"(lo), "=f"(hi) : "l"(v));
}
__device__ __forceinline__ u64 fma2(u64 a, u64 b, u64 c) {
    u64 d;
    asm("fma.rn.f32x2 %0, %1, %2, %3;" : "=l"(d) : "l"(a), "l"(b), "l"(c));
    return d;
}

// ================= Kernel 1: offset conv (3x3, 64 -> 18, pad 1) =================
// 256 CTAs x 128 threads. Each thread computes a PIXEL PAIR (P, P+128):
// the f32x2 pair dimension is the two pixels, so each weight LDS feeds 2 pixels.
// Weights duplicated in smem as (w,w) u64 so no per-step packing of B operand.
__global__ void __launch_bounds__(128, 2)
offset_conv_kernel(const float* __restrict__ x,
                   const float* __restrict__ wo,
                   const float* __restrict__ bo) {
    extern __shared__ u64 wdup[];           // [576][18] u64 = 82944 B
    for (int i = threadIdx.x; i < Q * 18; i += 128) {
        int q  = i / 18;
        int oc = i - q * 18;
        float v = wo[oc * Q + q];
        wdup[i] = pack2(v, v);
    }
    __syncthreads();

    int P0 = blockIdx.x * 256 + threadIdx.x;      // pixels P0 and P0+128
    int P1 = P0 + 128;
    int w  = P0 & 127;
    int h0 = (P0 >> 7) & 127;                     // even, h1 = h0+1 <= 127
    int h1 = h0 + 1;
    int b  = P0 >> 14;
    const float* xb = x + (size_t)b * Cs * HW;

    u64 acc[18];
#pragma unroll
    for (int j = 0; j < 18; j++) { float bv = bo[j]; acc[j] = pack2(bv, bv); }

#pragma unroll 1
    for (int k = 0; k < 9; k++) {
        int kh = k / 3, kw = k - kh * 3;
        int iy0 = h0 - 1 + kh, iy1 = h1 - 1 + kh, ix = w - 1 + kw;
        float vxf = (ix >= 0 && ix < Ws) ? 1.0f : 0.0f;
        float vf0 = ((iy0 >= 0 && iy0 < Hs) ? 1.0f : 0.0f) * vxf;
        float vf1 = ((iy1 >= 0 && iy1 < Hs) ? 1.0f : 0.0f) * vxf;
        int cy0 = min(max(iy0, 0), Hs - 1);
        int cy1 = min(max(iy1, 0), Hs - 1);
        int cx  = min(max(ix, 0), Ws - 1);
        const float* xp0 = xb + cy0 * Ws + cx;
        const float* xp1 = xb + cy1 * Ws + cx;
#pragma unroll 4
        for (int c = 0; c < Cs; c++) {
            float v0 = xp0[c * HW] * vf0;
            float v1 = xp1[c * HW] * vf1;
            u64 s2 = pack2(v0, v1);
            const ulonglong2* wr = (const ulonglong2*)&wdup[(c * 9 + k) * 18];
#pragma unroll
            for (int j = 0; j < 9; j++) {
                ulonglong2 ww = wr[j];
                acc[2 * j]     = fma2(s2, ww.x, acc[2 * j]);
                acc[2 * j + 1] = fma2(s2, ww.y, acc[2 * j + 1]);
            }
        }
    }

    // store: oc = 2k+d -> g_off[k][P][d]
#pragma unroll
    for (int j = 0; j < 18; j++) {
        float lo, hi;
        unpack2(acc[j], lo, hi);
        int k = j >> 1, d = j & 1;
        g_off[((k * 4 * HW) + P0) * 2 + d] = lo;
        g_off[((k * 4 * HW) + P1) * 2 + d] = hi;
    }
}

// ================= Kernel 2: deformable conv as staged tiled GEMM =================
// CTA tile: 128 pixels (one image row) x 64 outputs. K-loop over 9 kernel positions,
// each contributing a 64-deep GEMM chunk:
//   Phase A: sample bilinear values into S[c][128px] (coalesced LDG, conflict-free STS)
//   Phase B: smem GEMM, 8px x 4out register tile, FFMA2 pair = adjacent pixels.
__global__ void __launch_bounds__(256, 2)
deform_conv_kernel(const float* __restrict__ x,
                   const float* __restrict__ wd,
                   const float* __restrict__ bd,
                   float* __restrict__ out) {
    extern __shared__ float sm[];
    float* S  = sm;                 // [64][128]  32 KB
    float* Wk = sm + 64 * 128;      // [64][64]   16 KB

    int t     = threadIdx.x;
    int Pbase = blockIdx.x * 128;
    int h     = (Pbase >> 7) & 127;
    int b     = Pbase >> 14;
    const float* xb = x + (size_t)b * Cs * HW;

    // GEMM mapping: 16x16 threads -> (8px, 4out) tiles
    int tx  = t & 15, ty = t >> 4;
    int px0 = tx * 8, o0 = ty * 4;

    u64 acc[16];
#pragma unroll
    for (int o = 0; o < 4; o++) {
        float bv = bd[o0 + o];
#pragma unroll
        for (int pp = 0; pp < 4; pp++) acc[o * 4 + pp] = pack2(bv, bv);
    }

    // sampler mapping: 128 px x 2 channel-groups
    int spx  = t & 127;
    int cgrp = (t >> 7) * 32;
    int P    = Pbase + spx;

#pragma unroll 1
    for (int k = 0; k < 9; k++) {
        // load W chunk: Wk[c][o] = wd[o][c*9+k]
        for (int i = t; i < 64 * 64; i += 256) {
            int c = i & 63, o = i >> 6;
            Wk[c * 64 + o] = wd[o * Q + c * 9 + k];
        }
        // sample 64 channels at this kernel position
        int kh = k / 3, kw = k - kh * 3;
        float2 d = *(const float2*)&g_off[((k * 4 * HW) + P) * 2];
        float py = (float)(h - 1 + kh) + d.x;
        float px = (float)(spx - 1 + kw) + d.y;
        float y0f = floorf(py), x0f = floorf(px);
        int y0 = (int)y0f, x0 = (int)x0f;
        int y1 = y0 + 1,   x1 = x0 + 1;
        float wy1 = py - y0f, wy0 = 1.0f - wy1;
        float wx1 = px - x0f, wx0 = 1.0f - wx1;
        float vy0 = (y0 >= 0 && y0 < Hs) ? 1.0f : 0.0f;
        float vy1 = (y1 >= 0 && y1 < Hs) ? 1.0f : 0.0f;
        float vx0 = (x0 >= 0 && x0 < Ws) ? 1.0f : 0.0f;
        float vx1 = (x1 >= 0 && x1 < Ws) ? 1.0f : 0.0f;
        float w00 = wy0 * wx0 * vy0 * vx0;
        float w01 = wy0 * wx1 * vy0 * vx1;
        float w10 = wy1 * wx0 * vy1 * vx0;
        float w11 = wy1 * wx1 * vy1 * vx1;
        int cy0 = min(max(y0, 0), Hs - 1), cy1 = min(max(y1, 0), Hs - 1);
        int cx0 = min(max(x0, 0), Ws - 1), cx1 = min(max(x1, 0), Ws - 1);
        int o00 = cy0 * Ws + cx0, o01 = cy0 * Ws + cx1;
        int o10 = cy1 * Ws + cx0, o11 = cy1 * Ws + cx1;

        const float* xc = xb + cgrp * HW;
#pragma unroll 4
        for (int c = 0; c < 32; c++) {
            float s = fmaf(w00, xc[o00],
                      fmaf(w01, xc[o01],
                      fmaf(w10, xc[o10], w11 * xc[o11])));
            S[(cgrp + c) * 128 + spx] = s;
            xc += HW;
        }
        __syncthreads();

        // GEMM chunk: 64 K-steps
#pragma unroll 2
        for (int c = 0; c < 64; c++) {
            const ulonglong2* ap = (const ulonglong2*)&S[c * 128 + px0];
            ulonglong2 A01 = ap[0], A23 = ap[1];
            float4 bw = *(const float4*)&Wk[c * 64 + o0];
            u64 b0 = pack2(bw.x, bw.x);
            u64 b1 = pack2(bw.y, bw.y);
            u64 b2 = pack2(bw.z, bw.z);
            u64 b3 = pack2(bw.w, bw.w);
            acc[0]  = fma2(A01.x, b0, acc[0]);
            acc[1]  = fma2(A01.y, b0, acc[1]);
            acc[2]  = fma2(A23.x, b0, acc[2]);
            acc[3]  = fma2(A23.y, b0, acc[3]);
            acc[4]  = fma2(A01.x, b1, acc[4]);
            acc[5]  = fma2(A01.y, b1, acc[5]);
            acc[6]  = fma2(A23.x, b1, acc[6]);
            acc[7]  = fma2(A23.y, b1, acc[7]);
            acc[8]  = fma2(A01.x, b2, acc[8]);
            acc[9]  = fma2(A01.y, b2, acc[9]);
            acc[10] = fma2(A23.x, b2, acc[10]);
            acc[11] = fma2(A23.y, b2, acc[11]);
            acc[12] = fma2(A01.x, b3, acc[12]);
            acc[13] = fma2(A01.y, b3, acc[13]);
            acc[14] = fma2(A23.x, b3, acc[14]);
            acc[15] = fma2(A23.y, b3, acc[15]);
        }
        __syncthreads();
    }

    // epilogue: CTA = one image row; stores are contiguous u64 (2 adjacent px)
    float* op = out + (size_t)b * Os * HW + h * Ws;
#pragma unroll
    for (int o = 0; o < 4; o++) {
#pragma unroll
        for (int pp = 0; pp < 4; pp++) {
            *(u64*)&op[(o0 + o) * HW + px0 + 2 * pp] = acc[o * 4 + pp];
        }
    }
}

// ---------------- harness entry ----------------
extern "C" void kernel_launch(void* const* d_in, const int* in_sizes, int n_in,
                              void* d_out, int out_size) {
    const float* x  = (const float*)d_in[0];   // [4,64,128,128]
    const float* wo = (const float*)d_in[1];   // [18,64,3,3]
    const float* bo = (const float*)d_in[2];   // [18]
    const float* wd = (const float*)d_in[3];   // [64,64,3,3]
    const float* bd = (const float*)d_in[4];   // [64]
    float* out = (float*)d_out;                // [4,64,128,128]

    static int configured = 0;
    int off_smem = Q * 18 * (int)sizeof(u64);           // 82944
    int gem_smem = (64 * 128 + 64 * 64) * (int)sizeof(float);  // 49152
    cudaFuncSetAttribute(offset_conv_kernel,
                         cudaFuncAttributeMaxDynamicSharedMemorySize, off_smem);
    cudaFuncSetAttribute(deform_conv_kernel,
                         cudaFuncAttributeMaxDynamicSharedMemorySize, gem_smem);
    (void)configured;

    offset_conv_kernel<<<256, 128, off_smem>>>(x, wo, bo);
    deform_conv_kernel<<<512, 256, gem_smem>>>(x, wd, bd, out);
}

// round 3
// speedup vs baseline: 1.2810x; 1.2810x over previous
#include <cuda_runtime.h>
#include <math.h>

#define Hs   128
#define Ws   128
#define Cs   64
#define Os   64
#define HW   16384
#define Q    576          // Cs * 9

typedef unsigned long long u64;

// offsets, layout [k][b*HW] as u64 (dy,dx) pairs : coalesced access both kernels
__device__ u64 g_off[9 * 4 * HW];

// ---------------- packed f32x2 helpers (sm_100+) ----------------
__device__ __forceinline__ u64 pack2(float lo, float hi) {
    u64 r;
    asm("mov.b64 %0, {%1, %2};" : "=l"(r) : "f"(lo), "f"(hi));
    return r;
}
__device__ __forceinline__ void unpack2(u64 v, float& lo, float& hi) {
    asm("mov.b64 {%0, %1}, %2;" : "=f"(lo), "=f"(hi) : "l"(v));
}
__device__ __forceinline__ u64 fma2(u64 a, u64 b, u64 c) {
    u64 d;
    asm("fma.rn.f32x2 %0, %1, %2, %3;" : "=l"(d) : "l"(a), "l"(b), "l"(c));
    return d;
}

// ================= Kernel 1: offset conv (3x3, 64 -> 18, pad 1) =================
// Pixel-per-thread, f32x2 pair = two adjacent output channels (dy_k, dx_k).
// Weights in smem, padded row stride 20 floats so LDS.128 reads are 16B-aligned.
__global__ void __launch_bounds__(256, 4)
offset_conv_kernel(const float* __restrict__ x,
                   const float* __restrict__ wo,
                   const float* __restrict__ bo) {
    __shared__ float ws[Q * 20];              // 46080 B
    for (int i = threadIdx.x; i < Q * 18; i += 256) {
        int q  = i / 18;
        int oc = i - q * 18;
        ws[q * 20 + oc] = wo[oc * Q + q];
    }
    __syncthreads();

    int p = blockIdx.x * 256 + threadIdx.x;
    int w = p & 127;
    int h = (p >> 7) & 127;
    int b = p >> 14;
    const float* xb = x + (size_t)b * Cs * HW;

    u64 acc[9];
#pragma unroll
    for (int j = 0; j < 9; j++) acc[j] = pack2(bo[2 * j], bo[2 * j + 1]);

#pragma unroll 1
    for (int k = 0; k < 9; k++) {
        int kh = k / 3, kw = k - kh * 3;
        int iy = h - 1 + kh;
        int ix = w - 1 + kw;
        float vf = (iy >= 0 && iy < Hs && ix >= 0 && ix < Ws) ? 1.0f : 0.0f;
        int cy = min(max(iy, 0), Hs - 1);
        int cx = min(max(ix, 0), Ws - 1);
        const float* xp = xb + cy * Ws + cx;
#pragma unroll 2
        for (int c = 0; c < Cs; c++) {
            float val = __ldg(xp + c * HW) * vf;
            u64 s2 = pack2(val, val);
            const float* wr = &ws[(c * 9 + k) * 20];
            ulonglong2 w01 = *(const ulonglong2*)(wr);
            ulonglong2 w23 = *(const ulonglong2*)(wr + 4);
            ulonglong2 w45 = *(const ulonglong2*)(wr + 8);
            ulonglong2 w67 = *(const ulonglong2*)(wr + 12);
            u64        w8  = *(const u64*)(wr + 16);
            acc[0] = fma2(s2, w01.x, acc[0]);
            acc[1] = fma2(s2, w01.y, acc[1]);
            acc[2] = fma2(s2, w23.x, acc[2]);
            acc[3] = fma2(s2, w23.y, acc[3]);
            acc[4] = fma2(s2, w45.x, acc[4]);
            acc[5] = fma2(s2, w45.y, acc[5]);
            acc[6] = fma2(s2, w67.x, acc[6]);
            acc[7] = fma2(s2, w67.y, acc[7]);
            acc[8] = fma2(s2, w8,    acc[8]);
        }
    }

    // acc[k] = (dy_k, dx_k) for this pixel -> plane-k store, coalesced u64
#pragma unroll
    for (int k = 0; k < 9; k++) g_off[k * 4 * HW + p] = acc[k];
}

// ================= Kernel 2: deformable conv (fused, pixel-per-thread) =================
// 512 threads/CTA, 16 warps/SM, full weight matrix in smem (147 KB), no barriers
// in the main loop. Weights read as broadcast LDS.128 (2 u64 = 4 outputs each).
__global__ void __launch_bounds__(512, 1)
deform_conv_kernel(const float* __restrict__ x,
                   const float* __restrict__ wd,
                   const float* __restrict__ bd,
                   float* __restrict__ out) {
    extern __shared__ float ws[];   // [q][o] : 576*64 floats = 147456 B
    for (int i = threadIdx.x; i < Q * Os; i += 512) {
        int q = i >> 6;
        int o = i & 63;
        ws[i] = wd[o * Q + q];
    }
    __syncthreads();

    int p = blockIdx.x * 512 + threadIdx.x;
    int w = p & 127;
    int h = (p >> 7) & 127;
    int b = p >> 14;
    const float* xb = x + (size_t)b * Cs * HW;

    u64 acc[32];
    const float2* bd2 = (const float2*)bd;
#pragma unroll
    for (int j = 0; j < 32; j++) { float2 t = bd2[j]; acc[j] = pack2(t.x, t.y); }

#pragma unroll 1
    for (int k = 0; k < 9; k++) {
        int kh = k / 3, kw = k - kh * 3;
        float dlo, dhi;
        unpack2(g_off[k * 4 * HW + p], dlo, dhi);   // (dy, dx)
        float py = (float)(h - 1 + kh) + dlo;
        float px = (float)(w - 1 + kw) + dhi;
        float y0f = floorf(py), x0f = floorf(px);
        int y0 = (int)y0f, x0 = (int)x0f;
        int y1 = y0 + 1,   x1 = x0 + 1;
        float wy1 = py - y0f, wy0 = 1.0f - wy1;
        float wx1 = px - x0f, wx0 = 1.0f - wx1;
        float vy0 = (y0 >= 0 && y0 < Hs) ? 1.0f : 0.0f;
        float vy1 = (y1 >= 0 && y1 < Hs) ? 1.0f : 0.0f;
        float vx0 = (x0 >= 0 && x0 < Ws) ? 1.0f : 0.0f;
        float vx1 = (x1 >= 0 && x1 < Ws) ? 1.0f : 0.0f;
        float w00 = wy0 * wx0 * vy0 * vx0;
        float w01 = wy0 * wx1 * vy0 * vx1;
        float w10 = wy1 * wx0 * vy1 * vx0;
        float w11 = wy1 * wx1 * vy1 * vx1;
        int cy0 = min(max(y0, 0), Hs - 1), cy1 = min(max(y1, 0), Hs - 1);
        int cx0 = min(max(x0, 0), Ws - 1), cx1 = min(max(x1, 0), Ws - 1);
        int o00 = cy0 * Ws + cx0, o01 = cy0 * Ws + cx1;
        int o10 = cy1 * Ws + cx0, o11 = cy1 * Ws + cx1;

        const float* xc = xb;
#pragma unroll 2
        for (int c = 0; c < Cs; c++) {
            float s = fmaf(w00, __ldg(xc + o00),
                      fmaf(w01, __ldg(xc + o01),
                      fmaf(w10, __ldg(xc + o10), w11 * __ldg(xc + o11))));
            u64 s2 = pack2(s, s);
            const ulonglong2* wr = (const ulonglong2*)&ws[(c * 9 + k) * Os];
#pragma unroll
            for (int j = 0; j < 16; j++) {
                ulonglong2 ww = wr[j];
                acc[2 * j]     = fma2(s2, ww.x, acc[2 * j]);
                acc[2 * j + 1] = fma2(s2, ww.y, acc[2 * j + 1]);
            }
            xc += HW;
        }
    }

    float* op = out + (size_t)b * Os * HW + h * Ws + w;
#pragma unroll
    for (int j = 0; j < 32; j++) {
        float a0, a1;
        unpack2(acc[j], a0, a1);
        op[(2 * j) * HW]     = a0;
        op[(2 * j + 1) * HW] = a1;
    }
}

// ---------------- harness entry ----------------
extern "C" void kernel_launch(void* const* d_in, const int* in_sizes, int n_in,
                              void* d_out, int out_size) {
    const float* x  = (const float*)d_in[0];   // [4,64,128,128]
    const float* wo = (const float*)d_in[1];   // [18,64,3,3]
    const float* bo = (const float*)d_in[2];   // [18]
    const float* wd = (const float*)d_in[3];   // [64,64,3,3]
    const float* bd = (const float*)d_in[4];   // [64]
    float* out = (float*)d_out;                // [4,64,128,128]

    int gem_smem = Q * Os * (int)sizeof(float);   // 147456
    cudaFuncSetAttribute(deform_conv_kernel,
                         cudaFuncAttributeMaxDynamicSharedMemorySize, gem_smem);

    offset_conv_kernel<<<256, 256>>>(x, wo, bo);
    deform_conv_kernel<<<128, 512, gem_smem>>>(x, wd, bd, out);
}